// round 1
// baseline (speedup 1.0000x reference)
#include <cuda_runtime.h>
#include <cuda_bf16.h>

// CRF NLL: B=512, S=1024, T=64.
// inputs: 0 emissions (B,S,T) f32, 1 tags (B,S) i32, 2 mask (B,S) i32,
//         3 start (T) f32, 4 end (T) f32, 5 transitions (T,T) f32
// output: scalar f32 = -(sum_b ll_b) / (sum_b L_b)

#define B_ 512
#define S_ 1024
#define T_ 64

__device__ float g_ll[B_];
__device__ float g_len[B_];

typedef unsigned long long ull;

__device__ __forceinline__ ull ffma2(ull a, ull b, ull c) {
    ull d;
    asm("fma.rn.f32x2 %0, %1, %2, %3;" : "=l"(d) : "l"(a), "l"(b), "l"(c));
    return d;
}
__device__ __forceinline__ ull fadd2(ull a, ull b) {
    ull d;
    asm("add.rn.f32x2 %0, %1, %2;" : "=l"(d) : "l"(a), "l"(b));
    return d;
}
__device__ __forceinline__ ull pack2(float lo, float hi) {
    ull r;
    asm("mov.b64 %0, {%1, %2};" : "=l"(r) : "f"(lo), "f"(hi));
    return r;
}
__device__ __forceinline__ void unpack2(ull v, float& lo, float& hi) {
    asm("mov.b64 {%0, %1}, %2;" : "=f"(lo), "=f"(hi) : "l"(v));
}

// 4 warps per block, one batch per warp.
__global__ void __launch_bounds__(128) crf_main(
    const float* __restrict__ emis,
    const int* __restrict__ tags,
    const int* __restrict__ mask,
    const float* __restrict__ start,
    const float* __restrict__ endt,
    const float* __restrict__ trans)
{
    __shared__ __align__(16) float sh_ea[4][2][T_];  // per-warp, double-buffered

    const int lane = threadIdx.x & 31;
    const int wid  = threadIdx.x >> 5;
    const int b    = blockIdx.x * 4 + wid;
    if (b >= B_) return;

    const int j0 = 2 * lane;
    const int j1 = j0 + 1;

    // ---- Precompute E columns (exp(trans[i][j])) in registers, i-paired for f32x2 ----
    ull Ej0[T_ / 2];
    ull Ej1[T_ / 2];
#pragma unroll
    for (int k = 0; k < T_ / 2; k++) {
        float e0a = __expf(trans[(2 * k) * T_ + j0]);
        float e0b = __expf(trans[(2 * k + 1) * T_ + j0]);
        float e1a = __expf(trans[(2 * k) * T_ + j1]);
        float e1b = __expf(trans[(2 * k + 1) * T_ + j1]);
        Ej0[k] = pack2(e0a, e0b);
        Ej1[k] = pack2(e1a, e1b);
    }

    const int base = b * S_;

    // ---- sequence length L = sum(mask[b,:]) (mask is a prefix mask) ----
    int len_part = 0;
    for (int s = lane; s < S_; s += 32) len_part += mask[base + s];
#pragma unroll
    for (int o = 16; o > 0; o >>= 1) len_part += __shfl_xor_sync(0xffffffffu, len_part, o);
    const int L = len_part;  // in [512, 1024]

    // ---- numerator (gold-path score) ----
    float num = 0.0f;
    for (int s = 1 + lane; s < L; s += 32) {
        int tp = tags[base + s - 1];
        int tc = tags[base + s];
        num += trans[tp * T_ + tc] + emis[(size_t)b * S_ * T_ + s * T_ + tc];
    }
#pragma unroll
    for (int o = 16; o > 0; o >>= 1) num += __shfl_xor_sync(0xffffffffu, num, o);
    {
        int tg0 = tags[base];
        int tgl = tags[base + L - 1];
        // every lane computes the same value (broadcast loads); keeps num uniform
        num += start[tg0] + emis[(size_t)b * S_ * T_ + tg0] + endt[tgl];
    }

    // ---- forward recursion ----
    const float2* emp = (const float2*)(emis + (size_t)b * S_ * T_);
    float2 em0 = emp[lane];  // s = 0
    float a0 = start[j0] + em0.x;
    float a1 = start[j1] + em0.y;

    // distance-2 emission prefetch
    float2 p1 = emp[1 * (T_ / 2) + lane];
    float2 p2 = (2 < L) ? emp[2 * (T_ / 2) + lane] : p1;

    for (int s = 1; s < L; s++) {
        float2 ecur = p1;
        p1 = p2;
        int sp = s + 2;
        if (sp < L) p2 = emp[sp * (T_ / 2) + lane];

        // max over alpha (for stable exp)
        float m = fmaxf(a0, a1);
#pragma unroll
        for (int o = 16; o > 0; o >>= 1) m = fmaxf(m, __shfl_xor_sync(0xffffffffu, m, o));

        float ea0 = __expf(a0 - m);
        float ea1 = __expf(a1 - m);

        const int pb = s & 1;
        *(float2*)&sh_ea[wid][pb][j0] = make_float2(ea0, ea1);
        __syncwarp();

        const ulonglong2* q = (const ulonglong2*)sh_ea[wid][pb];
        ull acc00 = 0ull, acc01 = 0ull, acc10 = 0ull, acc11 = 0ull;
#pragma unroll
        for (int k = 0; k < 16; k++) {
            ulonglong2 v = q[k];  // ea[4k..4k+3] as two packed pairs
            acc00 = ffma2(v.x, Ej0[2 * k], acc00);
            acc01 = ffma2(v.y, Ej0[2 * k + 1], acc01);
            acc10 = ffma2(v.x, Ej1[2 * k], acc10);
            acc11 = ffma2(v.y, Ej1[2 * k + 1], acc11);
        }
        ull t0 = fadd2(acc00, acc01);
        ull t1 = fadd2(acc10, acc11);
        float s0lo, s0hi, s1lo, s1hi;
        unpack2(t0, s0lo, s0hi);
        unpack2(t1, s1lo, s1hi);
        float sum0 = s0lo + s0hi;
        float sum1 = s1lo + s1hi;

        a0 = m + __logf(sum0) + ecur.x;
        a1 = m + __logf(sum1) + ecur.y;
    }

    // ---- denominator = logsumexp(alpha + end) ----
    float v0 = a0 + endt[j0];
    float v1 = a1 + endt[j1];
    float m = fmaxf(v0, v1);
#pragma unroll
    for (int o = 16; o > 0; o >>= 1) m = fmaxf(m, __shfl_xor_sync(0xffffffffu, m, o));
    float e = __expf(v0 - m) + __expf(v1 - m);
#pragma unroll
    for (int o = 16; o > 0; o >>= 1) e += __shfl_xor_sync(0xffffffffu, e, o);
    float den = m + __logf(e);

    if (lane == 0) {
        g_ll[b]  = num - den;
        g_len[b] = (float)L;
    }
}

__global__ void crf_finalize(float* __restrict__ out) {
    __shared__ float s_ll[16];
    __shared__ float s_ln[16];
    int t = threadIdx.x;  // 512 threads
    float ll = g_ll[t];
    float ln = g_len[t];
#pragma unroll
    for (int o = 16; o > 0; o >>= 1) {
        ll += __shfl_xor_sync(0xffffffffu, ll, o);
        ln += __shfl_xor_sync(0xffffffffu, ln, o);
    }
    int w = t >> 5;
    if ((t & 31) == 0) { s_ll[w] = ll; s_ln[w] = ln; }
    __syncthreads();
    if (t == 0) {
        float sll = 0.0f, sln = 0.0f;
#pragma unroll
        for (int i = 0; i < 16; i++) { sll += s_ll[i]; sln += s_ln[i]; }
        out[0] = -(sll / sln);
    }
}

extern "C" void kernel_launch(void* const* d_in, const int* in_sizes, int n_in,
                              void* d_out, int out_size) {
    const float* emis  = (const float*)d_in[0];
    const int*   tags  = (const int*)d_in[1];
    const int*   mask  = (const int*)d_in[2];
    const float* start = (const float*)d_in[3];
    const float* endt  = (const float*)d_in[4];
    const float* trans = (const float*)d_in[5];
    float* out = (float*)d_out;

    crf_main<<<B_ / 4, 128>>>(emis, tags, mask, start, endt, trans);
    crf_finalize<<<1, B_>>>(out);
}

// round 3
// speedup vs baseline: 2.2350x; 2.2350x over previous
#include <cuda_runtime.h>
#include <cuda_bf16.h>

// CRF NLL: B=512, S=1024, T=64.
// inputs: 0 emissions (B,S,T) f32, 1 tags (B,S) i32, 2 mask (B,S) i32,
//         3 start (T) f32, 4 end (T) f32, 5 transitions (T,T) f32
// output: scalar f32 = -(sum_b ll_b) / (sum_b L_b)
//
// Scaled linear-domain forward algorithm: w[j] ~ exp(alpha[j]) * 2^-csum.
// Rescale exponent k is sampled from w immediately AFTER each update
// (stable: x' = frac(x) + g), applied at the next step; the shfl sits in
// the latency shadow of the next matvec. No exp/log on the recursion chain.

#define B_ 512
#define S_ 1024
#define T_ 64
#define FULLMASK 0xffffffffu

__device__ float g_ll[B_];
__device__ float g_len[B_];

typedef unsigned long long ull;

__device__ __forceinline__ ull ffma2(ull a, ull b, ull c) {
    ull d;
    asm("fma.rn.f32x2 %0, %1, %2, %3;" : "=l"(d) : "l"(a), "l"(b), "l"(c));
    return d;
}
__device__ __forceinline__ ull fadd2(ull a, ull b) {
    ull d;
    asm("add.rn.f32x2 %0, %1, %2;" : "=l"(d) : "l"(a), "l"(b));
    return d;
}
__device__ __forceinline__ ull pack2(float lo, float hi) {
    ull r;
    asm("mov.b64 %0, {%1, %2};" : "=l"(r) : "f"(lo), "f"(hi));
    return r;
}
__device__ __forceinline__ void unpack2(ull v, float& lo, float& hi) {
    asm("mov.b64 {%0, %1}, %2;" : "=f"(lo), "=f"(hi) : "l"(v));
}

// 4 warps per block, one batch per warp.
__global__ void __launch_bounds__(128) crf_main(
    const float* __restrict__ emis,
    const int* __restrict__ tags,
    const int* __restrict__ mask,
    const float* __restrict__ start,
    const float* __restrict__ endt,
    const float* __restrict__ trans)
{
    __shared__ __align__(16) float sh_w[4][2][T_];  // per-warp, double-buffered

    const int lane = threadIdx.x & 31;
    const int wid  = threadIdx.x >> 5;
    const int b    = blockIdx.x * 4 + wid;

    const int j0 = 2 * lane;
    const int j1 = j0 + 1;

    // ---- E = exp(trans), columns j0/j1, i-paired for f32x2 ----
    ull Ej0[T_ / 2];
    ull Ej1[T_ / 2];
#pragma unroll
    for (int m = 0; m < T_ / 2; m++) {
        float2 ra = *(const float2*)&trans[(2 * m) * T_ + j0];
        float2 rb = *(const float2*)&trans[(2 * m + 1) * T_ + j0];
        Ej0[m] = pack2(__expf(ra.x), __expf(rb.x));
        Ej1[m] = pack2(__expf(ra.y), __expf(rb.y));
    }

    const int base = b * S_;

    // ---- sequence length L (prefix mask) ----
    int len_part = 0;
    for (int s = lane; s < S_; s += 32) len_part += mask[base + s];
#pragma unroll
    for (int o = 16; o > 0; o >>= 1) len_part += __shfl_xor_sync(FULLMASK, len_part, o);
    const int L = len_part;

    // ---- numerator (gold-path score) ----
    float num = 0.0f;
    for (int s = 1 + lane; s < L; s += 32) {
        int tp = tags[base + s - 1];
        int tc = tags[base + s];
        num += trans[tp * T_ + tc] + emis[(size_t)b * S_ * T_ + s * T_ + tc];
    }
#pragma unroll
    for (int o = 16; o > 0; o >>= 1) num += __shfl_xor_sync(FULLMASK, num, o);
    {
        int tg0 = tags[base];
        int tgl = tags[base + L - 1];
        num += start[tg0] + emis[(size_t)b * S_ * T_ + tg0] + endt[tgl];
    }

    // ---- forward recursion (scaled linear domain) ----
    const float2* emp = (const float2*)(emis + (size_t)b * S_ * T_);
    float2 em0 = emp[lane];  // s = 0
    float w0 = __expf(start[j0] + em0.x);
    float w1 = __expf(start[j1] + em0.y);

    // emission prefetch: F = exp(em[s]) for current step; p1=em[s+1], p2=em[s+2]
    float2 p1 = emp[1 * (T_ / 2) + lane];
    float2 p2 = emp[2 * (T_ / 2) + lane];
    float F0 = __expf(p1.x);
    float F1 = __expf(p1.y);
    p1 = p2;
    p2 = emp[3 * (T_ / 2) + lane];

    // initial rescale: sample k from the initial w (warp-uniform via lane 0)
    float r;
    int   kcur;
    {
        float w00 = __shfl_sync(FULLMASK, w0, 0);
        int k = ((__float_as_int(w00) >> 23) & 0xff) - 127;
        k = max(-126, min(126, k));
        r = __int_as_float((127 - k) << 23);
        kcur = k;
    }
    float csum = 0.0f;  // sum of applied k's (exact: small integers)

    for (int s = 1; s < L; s++) {
        const int pb = s & 1;
        *(float2*)&sh_w[wid][pb][j0] = make_float2(w0, w1);
        __syncwarp();

        // off-chain: exp(em[s+1]) for next step, advance prefetch
        float Fn0 = __expf(p1.x);
        float Fn1 = __expf(p1.y);
        p1 = p2;
        int sp = s + 3; if (sp >= S_) sp = S_ - 1;
        p2 = emp[sp * (T_ / 2) + lane];

        // matvec: v[j] = sum_i w[i] * E[i][j]
        const ulonglong2* q = (const ulonglong2*)sh_w[wid][pb];
        ull a00 = 0ull, a01 = 0ull, a02 = 0ull, a03 = 0ull;
        ull a10 = 0ull, a11 = 0ull, a12 = 0ull, a13 = 0ull;
#pragma unroll
        for (int m = 0; m < 8; m++) {
            ulonglong2 va = q[2 * m];      // w[8m..8m+3]
            ulonglong2 vb = q[2 * m + 1];  // w[8m+4..8m+7]
            a00 = ffma2(va.x, Ej0[4 * m + 0], a00);
            a01 = ffma2(va.y, Ej0[4 * m + 1], a01);
            a02 = ffma2(vb.x, Ej0[4 * m + 2], a02);
            a03 = ffma2(vb.y, Ej0[4 * m + 3], a03);
            a10 = ffma2(va.x, Ej1[4 * m + 0], a10);
            a11 = ffma2(va.y, Ej1[4 * m + 1], a11);
            a12 = ffma2(vb.x, Ej1[4 * m + 2], a12);
            a13 = ffma2(vb.y, Ej1[4 * m + 3], a13);
        }
        ull t0 = fadd2(fadd2(a00, a01), fadd2(a02, a03));
        ull t1 = fadd2(fadd2(a10, a11), fadd2(a12, a13));
        float s0l, s0h, s1l, s1h;
        unpack2(t0, s0l, s0h);
        unpack2(t1, s1l, s1h);

        // apply emission + pending rescale (r = 2^-kcur, from PREVIOUS w)
        w0 = (s0l + s0h) * (F0 * r);
        w1 = (s1l + s1h) * (F1 * r);
        csum += (float)kcur;

        // sample k from the w JUST computed (stable: x' = frac(x) + g).
        // shfl + int ops sit in the latency shadow of the next matvec.
        float w00 = __shfl_sync(FULLMASK, w0, 0);
        int k = ((__float_as_int(w00) >> 23) & 0xff) - 127;
        k = max(-126, min(126, k));
        r = __int_as_float((127 - k) << 23);
        kcur = k;

        F0 = Fn0;
        F1 = Fn1;
    }

    // ---- denominator = csum*ln2 + log( sum_j w[j]*exp(end[j]) ) ----
    float e = w0 * __expf(endt[j0]) + w1 * __expf(endt[j1]);
#pragma unroll
    for (int o = 16; o > 0; o >>= 1) e += __shfl_xor_sync(FULLMASK, e, o);
    float den = (float)((double)csum * 0.6931471805599453) + __logf(e);

    if (lane == 0) {
        g_ll[b]  = num - den;
        g_len[b] = (float)L;
    }
}

__global__ void crf_finalize(float* __restrict__ out) {
    __shared__ float s_ll[16];
    __shared__ float s_ln[16];
    int t = threadIdx.x;  // 512 threads
    float ll = g_ll[t];
    float ln = g_len[t];
#pragma unroll
    for (int o = 16; o > 0; o >>= 1) {
        ll += __shfl_xor_sync(FULLMASK, ll, o);
        ln += __shfl_xor_sync(FULLMASK, ln, o);
    }
    int w = t >> 5;
    if ((t & 31) == 0) { s_ll[w] = ll; s_ln[w] = ln; }
    __syncthreads();
    if (t == 0) {
        float sll = 0.0f, sln = 0.0f;
#pragma unroll
        for (int i = 0; i < 16; i++) { sll += s_ll[i]; sln += s_ln[i]; }
        out[0] = -(sll / sln);
    }
}

extern "C" void kernel_launch(void* const* d_in, const int* in_sizes, int n_in,
                              void* d_out, int out_size) {
    const float* emis  = (const float*)d_in[0];
    const int*   tags  = (const int*)d_in[1];
    const int*   mask  = (const int*)d_in[2];
    const float* start = (const float*)d_in[3];
    const float* endt  = (const float*)d_in[4];
    const float* trans = (const float*)d_in[5];
    float* out = (float*)d_out;

    crf_main<<<B_ / 4, 128>>>(emis, tags, mask, start, endt, trans);
    crf_finalize<<<1, B_>>>(out);
}